// round 9
// baseline (speedup 1.0000x reference)
#include <cuda_runtime.h>
#include <cstdint>

#define T_LEN   730
#define B_LEN   1000
#define LENF    15
#define NEARZERO 1e-5f

#define SCAN_BLOCKS 125          // blocks 0..124: scan; block 125: unit hydrograph
#define NBLK        126
#define BLK_T       512
#define UG 10
#define NGROUPS 73               // 73*10 = 730

// smem layout (floats): per (slot, step, basin): 44-float region
//   [0..15]  (avail, Snew) for channel ch at 2*ch
//   [16..31] (Gnew,  Y)    for channel ch at 16+2*ch
#define BAS_S  44
#define STEP_S 356
#define SLOT_S (STEP_S * UG)     // 3560
#define SRED_FLOATS (2 * SLOT_S)

__device__ float g_qsurf[T_LEN * B_LEN];
__device__ float g_qgw  [T_LEN * B_LEN];
__device__ float g_uh   [B_LEN * LENF];

__device__ unsigned g_count = 0;
__device__ unsigned g_sense = 0;

__device__ __forceinline__ void grid_barrier() {
    __syncthreads();
    if (threadIdx.x == 0) {
        volatile unsigned* vs = &g_sense;
        unsigned s = *vs;
        __threadfence();
        if (atomicAdd(&g_count, 1u) == NBLK - 1u) {
            g_count = 0;
            __threadfence();
            *vs = s ^ 1u;
        } else {
            while (*vs == s) { }
            __threadfence();
        }
    }
    __syncthreads();
}

__device__ __forceinline__ float f_sqrt_approx(float x) {
    float r; asm("sqrt.approx.f32 %0, %1;" : "=f"(r) : "f"(x)); return r;
}
// exp(-z) for z in [0, 0.1]: 4-term Horner, |err| < 1e-7
__device__ __forceinline__ float expm_poly(float z) {
    float e = fmaf(z, 1.0f / 24.0f, -1.0f / 6.0f);
    e = fmaf(z, e, 0.5f);
    e = fmaf(z, e, -1.0f);
    e = fmaf(z, e, 1.0f);
    return e;
}

// named barriers: 32 producers (arrive) + 64 consumers (sync) = 96 arrivals
#define BAR_SYNC(id)   asm volatile("bar.sync %0, 96;"   :: "r"(id) : "memory")
#define BAR_ARRIVE(id) asm volatile("bar.arrive %0, 96;" :: "r"(id) : "memory")

// ---------------------------------------------------------------------------
__device__ void uh_for_basin(const float* __restrict__ raw, int b) {
    float ra = raw[b * 34 + 32] * 2.9f;
    float rb = raw[b * 34 + 33] * 6.5f;
    float aa    = fmaxf(ra, 0.0f) + 0.1f;
    float theta = fmaxf(rb, 0.0f) + 0.5f;
    float lg   = lgammaf(aa);
    float lth  = logf(theta);
    float ivth = 1.0f / theta;
    float w[LENF];
    float s = 0.0f;
#pragma unroll
    for (int k = 0; k < LENF; ++k) {
        float t = (float)k + 0.5f;
        float lw = (aa - 1.0f) * logf(t) - t * ivth - lg - aa * lth;
        w[k] = expf(lw);
        s += w[k];
    }
    float inv = 1.0f / s;
#pragma unroll
    for (int k = 0; k < LENF; ++k)
        g_uh[b * LENF + k] = w[k] * inv;
}

// ---------------------------------------------------------------------------
__global__ void __launch_bounds__(BLK_T) fused_kernel(
    const float* __restrict__ x,      // (T,B,2)
    const float* __restrict__ raw,    // (B,34)
    float* __restrict__ out)          // (T,B,6)
{
    __shared__ __align__(16) float sred[SRED_FLOATS];
    const int tid = threadIdx.x;

    if (blockIdx.x == SCAN_BLOCKS) {
        for (int b = tid; b < B_LEN; b += BLK_T) uh_for_basin(raw, b);
    } else if (tid < 32) {
        // ===== producer warp: 2 interleaved chains per thread =====
        int bl = tid >> 2;                 // basin-local 0..7
        int m  = tid & 3;                  // chain A = m, chain B = m+4
        int b  = blockIdx.x * 8 + bl;
        int mA = m, mB = m + 4;

        // chain A params
        float aA  = fmaf(raw[b*34 +      mA], 0.9f, 0.1f);
        float bbA = fmaf(raw[b*34 +  8 + mA], 450.0f, 50.0f);
        float cA  = raw[b*34 + 16 + mA];
        float dA  = fmaf(raw[b*34 + 24 + mA], 0.89f, 0.01f);
        // chain B params
        float aB  = fmaf(raw[b*34 +      mB], 0.9f, 0.1f);
        float bbB = fmaf(raw[b*34 +  8 + mB], 450.0f, 50.0f);
        float cB  = raw[b*34 + 16 + mB];
        float dB  = fmaf(raw[b*34 + 24 + mB], 0.89f, 0.01f);

        float inv2aA = 0.5f / aA,  inv2aB = 0.5f / aB;
        float binv2aA = bbA * inv2aA, binv2aB = bbB * inv2aB;
        float boaA = bbA / aA, boaB = bbB / aB;
        float invbA = 1.0f / bbA, invbB = 1.0f / bbB;
        float inv1pdA = 1.0f / (1.0f + dA), inv1pdB = 1.0f / (1.0f + dB);

        float SA = 50.0f, GA = 10.0f;
        float SB = 50.0f, GB = 10.0f;

        float2* p1A = (float2*)(sred + bl * BAS_S + 2 * mA);
        float2* p1B = (float2*)(sred + bl * BAS_S + 2 * mB);
        float2* p2A = (float2*)(sred + bl * BAS_S + 16 + 2 * mA);
        float2* p2B = (float2*)(sred + bl * BAS_S + 16 + 2 * mB);

        const float2* __restrict__ xv = (const float2*)x;
        float2 cur[UG], nxt[UG];
#pragma unroll
        for (int i = 0; i < UG; ++i) cur[i] = __ldg(xv + i * B_LEN + b);

        for (int gi = 0; gi < NGROUPS; ++gi) {
            if (gi < NGROUPS - 1) {
                const float2* base = xv + (gi + 1) * UG * B_LEN + b;
#pragma unroll
                for (int i = 0; i < UG; ++i) nxt[i] = __ldg(base + i * B_LEN);
            }
            int slot = gi & 1;
            if (gi >= 2) BAR_SYNC(3 + slot);
            int so = slot * (SLOT_S / 2);   // float2 units
#pragma unroll
            for (int i = 0; i < UG; ++i) {
                float p   = cur[i].x;
                float pet = cur[i].y;

                // chain A
                float WA    = p + SA;
                float termA = fmaf(WA, inv2aA, binv2aA);
                float argA  = fmaxf(fmaf(termA, termA, -(WA * boaA)), NEARZERO);
                // chain B
                float WB    = p + SB;
                float termB = fmaf(WB, inv2aB, binv2aB);
                float argB  = fmaxf(fmaf(termB, termB, -(WB * boaB)), NEARZERO);

                float sqA = f_sqrt_approx(argA);
                float sqB = f_sqrt_approx(argB);
                float efA = expm_poly(pet * invbA);
                float efB = expm_poly(pet * invbB);

                float YA = termA - sqA;
                float YB = termB - sqB;
                float SnA = YA * efA;
                float SnB = YB * efB;
                float avA = WA - YA;
                float avB = WB - YB;
                float GnA = fmaf(cA, avA, GA) * inv1pdA;
                float GnB = fmaf(cB, avB, GB) * inv1pdB;
                SA = SnA; GA = GnA;
                SB = SnB; GB = GnB;

                int o2 = so + i * (STEP_S / 2);
                p1A[o2] = make_float2(avA, SnA);
                p1B[o2] = make_float2(avB, SnB);
                p2A[o2] = make_float2(GnA, YA);
                p2B[o2] = make_float2(GnB, YB);
            }
            BAR_ARRIVE(1 + slot);
            if (gi < NGROUPS - 1) {
#pragma unroll
                for (int i = 0; i < UG; ++i) cur[i] = nxt[i];
            }
        }
    } else if (tid >= 64 && tid < 128) {
        // ============ consumers: all 5 outputs per (basin, step) ============
        int rtid = tid - 64;
        bool active = (rtid < 40);
        int bl = rtid & 7;
        int s0 = rtid >> 3;          // 0..4 for active lanes
        int b  = blockIdx.x * 8 + bl;

        float wq[8], wd[8];
#pragma unroll
        for (int k = 0; k < 8; ++k) {
            wq[k] = 1.0f - raw[b*34 + 16 + k];                    // (1-c)
            wd[k] = fmaf(raw[b*34 + 24 + k], 0.89f, 0.01f);       // d
        }

        const float* base0 = sred + bl * BAS_S;

        for (int gi = 0; gi < NGROUPS; ++gi) {
            int slot = gi & 1;
            BAR_SYNC(1 + slot);
            if (active) {
                int tbase = gi * UG;
#pragma unroll
                for (int half = 0; half < 2; ++half) {
                    int s = s0 + half * 5;
                    int t = tbase + s;
                    const float4* p1 = (const float4*)(base0 + slot * SLOT_S + s * STEP_S);
                    const float4* p2 = (const float4*)(base0 + slot * SLOT_S + s * STEP_S + 16);
                    float4 A0 = p1[0], A1 = p1[1], A2 = p1[2], A3 = p1[3];
                    float4 B0 = p2[0], B1 = p2[1], B2 = p2[2], B3 = p2[3];

                    float sumS = ((A0.y + A0.w) + (A1.y + A1.w))
                               + ((A2.y + A2.w) + (A3.y + A3.w));
                    float sumG = ((B0.x + B0.z) + (B1.x + B1.z))
                               + ((B2.x + B2.z) + (B3.x + B3.z));
                    float sumY = ((B0.y + B0.w) + (B1.y + B1.w))
                               + ((B2.y + B2.w) + (B3.y + B3.w));
                    float dQS = wq[0]*A0.x + wq[1]*A0.z + wq[2]*A1.x + wq[3]*A1.z
                              + wq[4]*A2.x + wq[5]*A2.z + wq[6]*A3.x + wq[7]*A3.z;
                    float dQG = wd[0]*B0.x + wd[1]*B0.z + wd[2]*B1.x + wd[3]*B1.z
                              + wd[4]*B2.x + wd[5]*B2.z + wd[6]*B3.x + wd[7]*B3.z;

                    g_qsurf[t * B_LEN + b] = dQS * 0.125f;
                    g_qgw  [t * B_LEN + b] = dQG * 0.125f;
                    float* o = out + t * (6 * B_LEN) + b * 6;
                    o[3] = (sumY - sumS) * 0.125f;
                    o[4] = sumS * 0.125f;
                    o[5] = sumG * 0.125f;
                }
            }
            BAR_ARRIVE(3 + slot);
        }
    }

    // ===================== barrier =====================
    grid_barrier();

    // ===================== Phase 2: conv (TPER=5) =====================
    const int nItems = (T_LEN / 5) * B_LEN;   // 146000
    for (int item = blockIdx.x * BLK_T + tid; item < nItems; item += NBLK * BLK_T) {
        int b  = item % B_LEN;
        int t0 = (item / B_LEN) * 5;

        float uh[LENF];
#pragma unroll
        for (int k = 0; k < LENF; ++k) uh[k] = __ldg(&g_uh[b * LENF + k]);

        float qs1[LENF - 1 + 5];
        float qs2[LENF - 1 + 5];
#pragma unroll
        for (int i = 0; i < LENF - 1 + 5; ++i) {
            int tt = t0 - (LENF - 1) + i;
            bool ok = (tt >= 0);
            qs1[i] = ok ? __ldg(&g_qsurf[tt * B_LEN + b]) : 0.0f;
            qs2[i] = ok ? __ldg(&g_qgw  [tt * B_LEN + b]) : 0.0f;
        }
#pragma unroll
        for (int j = 0; j < 5; ++j) {
            float a1 = 0.0f, a2 = 0.0f;
#pragma unroll
            for (int k = 0; k < LENF; ++k) {
                a1 = fmaf(uh[k], qs1[LENF - 1 + j - k], a1);
                a2 = fmaf(uh[k], qs2[LENF - 1 + j - k], a2);
            }
            float* o = out + (t0 + j) * (6 * B_LEN) + b * 6;
            o[0] = a1 + a2;   // routed Qsim (conv is linear)
            o[1] = a1;        // routed Qsurf
            o[2] = a2;        // routed Qgw
        }
    }
}

// ---------------------------------------------------------------------------
extern "C" void kernel_launch(void* const* d_in, const int* in_sizes, int n_in,
                              void* d_out, int out_size) {
    const float* x   = (const float*)d_in[0];   // (730,1000,2)
    const float* raw = (const float*)d_in[1];   // (1000,34)
    float* out = (float*)d_out;                 // (730,1000,6)

    fused_kernel<<<NBLK, BLK_T>>>(x, raw, out);
}

// round 10
// speedup vs baseline: 2.2334x; 2.2334x over previous
#include <cuda_runtime.h>
#include <cstdint>

#define T_LEN   730
#define B_LEN   1000
#define LENF    15
#define NEARZERO 1e-5f

#define NBLK  125                // 8 basins per block
#define BLK_T 128                // warps 0,1: producers; warp2: conv; warp3: sums
#define UG 10
#define NGROUPS 73               // 73*10 = 730

// smem layout (R7-proven): per (slot, step, basin): [q][m], q stride 8, basin stride 44
#define Q_S    8
#define BAS_S  44
#define STEP_S 356
#define SLOT_S (STEP_S * UG)     // 3560 floats
#define SRED_FLOATS (2 * SLOT_S)

__device__ __forceinline__ float f_sqrt_approx(float x) {
    float r; asm("sqrt.approx.f32 %0, %1;" : "=f"(r) : "f"(x)); return r;
}
__device__ __forceinline__ float f_ex2(float x) {
    float r; asm("ex2.approx.f32 %0, %1;" : "=f"(r) : "f"(x)); return r;
}

// named barriers: 64 producers + 64 consumers (warps 2,3) = 128 arrivals
#define BAR_SYNC(id)   asm volatile("bar.sync %0, 128;"   :: "r"(id) : "memory")
#define BAR_ARRIVE(id) asm volatile("bar.arrive %0, 128;" :: "r"(id) : "memory")

__global__ void __launch_bounds__(BLK_T) fused_kernel(
    const float* __restrict__ x,      // (T,B,2)
    const float* __restrict__ raw,    // (B,34)
    float* __restrict__ out)          // (T,B,6)
{
    __shared__ __align__(16) float sred[SRED_FLOATS];
    const int tid = threadIdx.x;

    if (tid < 64) {
        // =============== producers (R7-verbatim): 1 chain/thread ===============
        int bl = tid >> 3;
        int m  = tid & 7;
        int b  = blockIdx.x * 8 + bl;

        float a   = fmaf(raw[b*34 +      m], 0.9f, 0.1f);
        float bb  = fmaf(raw[b*34 +  8 + m], 450.0f, 50.0f);
        float c   = raw[b*34 + 16 + m];
        float d   = fmaf(raw[b*34 + 24 + m], 0.89f, 0.01f);

        float inv2a  = 0.5f / a;
        float binv2a = bb * inv2a;
        float boa    = bb / a;
        float nl2eob = -1.44269504088896f / bb;
        float onemc  = 1.0f - c;
        float inv1pd = 1.0f / (1.0f + d);

        float S = 50.0f, G = 10.0f;

        float* my = sred + bl * BAS_S + m;

        const float2* __restrict__ xv = (const float2*)x;
        float2 cur[UG], nxt[UG];
#pragma unroll
        for (int i = 0; i < UG; ++i) cur[i] = __ldg(xv + i * B_LEN + b);

        for (int gi = 0; gi < NGROUPS; ++gi) {
            if (gi < NGROUPS - 1) {
                const float2* base = xv + (gi + 1) * UG * B_LEN + b;
#pragma unroll
                for (int i = 0; i < UG; ++i) nxt[i] = __ldg(base + i * B_LEN);
            }
            int slot = gi & 1;
            if (gi >= 2) BAR_SYNC(3 + slot);
            float* sb = my + slot * SLOT_S;
#pragma unroll
            for (int i = 0; i < UG; ++i) {
                float p   = cur[i].x;
                float pet = cur[i].y;
                float W    = p + S;
                float term = fmaf(W, inv2a, binv2a);
                float arg  = fmaxf(fmaf(term, term, -(W * boa)), NEARZERO);
                float Y    = term - f_sqrt_approx(arg);
                float Snew = Y * f_ex2(pet * nl2eob);
                float avail = W - Y;
                float vqs  = onemc * avail;
                float Gnew = fmaf(c, avail, G) * inv1pd;
                float vqg  = d * Gnew;
                float vae  = Y - Snew;
                S = Snew;
                G = Gnew;
                float* sl = sb + i * STEP_S;
                sl[0 * Q_S] = vqs;
                sl[1 * Q_S] = vqg;
                sl[2 * Q_S] = vae;
                sl[3 * Q_S] = Snew;
                sl[4 * Q_S] = Gnew;
            }
            BAR_ARRIVE(1 + slot);
            if (gi < NGROUPS - 1) {
#pragma unroll
                for (int i = 0; i < UG; ++i) cur[i] = nxt[i];
            }
        }
    } else if (tid < 96) {
        // ========= warp2: inline convolution lanes =========
        // lane 0..7  : qsurf conv for basin bl  (stores cols 0,1)
        // lane 8..15 : qgw   conv for basin bl  (stores col 2)
        int lane   = tid - 64;
        bool active = (lane < 16);
        int bl     = lane & 7;
        int series = lane >> 3;              // 0 = qsurf (q=0), 1 = qgw (q=1)
        int b      = blockIdx.x * 8 + bl;

        // --- prologue: gamma unit hydrograph for this basin, pre-scaled by 1/8 ---
        float uh[LENF];
        if (active) {
            float ra = raw[b * 34 + 32] * 2.9f;
            float rb = raw[b * 34 + 33] * 6.5f;
            float aa    = fmaxf(ra, 0.0f) + 0.1f;
            float theta = fmaxf(rb, 0.0f) + 0.5f;
            float lg   = lgammaf(aa);
            float lth  = logf(theta);
            float ivth = 1.0f / theta;
            float s = 0.0f;
#pragma unroll
            for (int k = 0; k < LENF; ++k) {
                float t = (float)k + 0.5f;
                float lw = (aa - 1.0f) * logf(t) - t * ivth - lg - aa * lth;
                uh[k] = expf(lw);
                s += uh[k];
            }
            float inv = 0.125f / s;          // fold the NMUL mean into the kernel
#pragma unroll
            for (int k = 0; k < LENF; ++k) uh[k] *= inv;
        } else {
#pragma unroll
            for (int k = 0; k < LENF; ++k) uh[k] = 0.0f;
        }

        // conv ring: r[j] = contribution to out(t+1+j) from q[<=t]
        float r[LENF - 1];
#pragma unroll
        for (int k = 0; k < LENF - 1; ++k) r[k] = 0.0f;

        const float* base0 = sred + bl * BAS_S + series * Q_S;

        for (int gi = 0; gi < NGROUPS; ++gi) {
            int slot = gi & 1;
            BAR_SYNC(1 + slot);
            if (active) {
                const float* sb = base0 + slot * SLOT_S;
                int tbase = gi * UG;
#pragma unroll
                for (int i = 0; i < UG; ++i) {
                    const float4* p4 = (const float4*)(sb + i * STEP_S);
                    float4 v0 = p4[0];
                    float4 v1 = p4[1];
                    float q = ((v0.x + v0.y) + (v0.z + v0.w))
                            + ((v1.x + v1.y) + (v1.z + v1.w));   // raw 8-sum

                    float mine = fmaf(q, uh[0], r[0]);           // routed value at t
                    // shift ring
#pragma unroll
                    for (int j = 0; j < LENF - 2; ++j)
                        r[j] = fmaf(q, uh[j + 1], r[j + 1]);
                    r[LENF - 2] = q * uh[LENF - 1];

                    float other = __shfl_xor_sync(0xffffu, mine, 8);
                    int t = tbase + i;
                    float* o = out + t * (6 * B_LEN) + b * 6;
                    if (series == 0) {
                        *(float2*)o = make_float2(mine + other, mine); // cols 0,1
                    } else {
                        o[2] = mine;                                   // col 2
                    }
                }
            }
            BAR_ARRIVE(3 + slot);
        }
    } else {
        // ========= warp3: plain mean lanes (cols 3,4,5) =========
        int lane = tid - 96;
        bool active = (lane < 24);
        int bl = lane & 7;
        int j  = lane >> 3;                  // 0: AET(q=2), 1: S(q=3), 2: G(q=4)
        int b  = blockIdx.x * 8 + bl;

        const float* base0 = sred + bl * BAS_S + (2 + j) * Q_S;

        for (int gi = 0; gi < NGROUPS; ++gi) {
            int slot = gi & 1;
            BAR_SYNC(1 + slot);
            if (active) {
                const float* sb = base0 + slot * SLOT_S;
                int tbase = gi * UG;
#pragma unroll
                for (int i = 0; i < UG; ++i) {
                    const float4* p4 = (const float4*)(sb + i * STEP_S);
                    float4 v0 = p4[0];
                    float4 v1 = p4[1];
                    float s = ((v0.x + v0.y) + (v0.z + v0.w))
                            + ((v1.x + v1.y) + (v1.z + v1.w));
                    int t = tbase + i;
                    out[t * (6 * B_LEN) + b * 6 + 3 + j] = s * 0.125f;
                }
            }
            BAR_ARRIVE(3 + slot);
        }
    }
}

// ---------------------------------------------------------------------------
extern "C" void kernel_launch(void* const* d_in, const int* in_sizes, int n_in,
                              void* d_out, int out_size) {
    const float* x   = (const float*)d_in[0];   // (730,1000,2)
    const float* raw = (const float*)d_in[1];   // (1000,34)
    float* out = (float*)d_out;                 // (730,1000,6)

    fused_kernel<<<NBLK, BLK_T>>>(x, raw, out);
}

// round 12
// speedup vs baseline: 2.4516x; 1.0977x over previous
#include <cuda_runtime.h>
#include <cstdint>

#define T_LEN   730
#define B_LEN   1000
#define LENF    15
#define NEARZERO 1e-5f

#define NBLK  125                // 8 basins per block
#define BLK_T 128                // warps 0,1: producers; warp2: conv; warp3: sums
#define UG 10
#define NGROUPS 73               // 73*10 = 730

// smem layout: per (slot, step, basin): [q][m], q stride 8, basin stride 44
#define Q_S    8
#define BAS_S  44
#define STEP_S 356
#define SLOT_S (STEP_S * UG)     // 3560 floats
#define SRED_FLOATS (2 * SLOT_S)

__device__ __forceinline__ float f_sqrt_approx(float x) {
    float r; asm("sqrt.approx.f32 %0, %1;" : "=f"(r) : "f"(x)); return r;
}
__device__ __forceinline__ float f_ex2(float x) {
    float r; asm("ex2.approx.f32 %0, %1;" : "=f"(r) : "f"(x)); return r;
}

// named barriers: 64 producers + 64 consumers (warps 2,3) = 128 arrivals
#define BAR_SYNC(id)   asm volatile("bar.sync %0, 128;"   :: "r"(id) : "memory")
#define BAR_ARRIVE(id) asm volatile("bar.arrive %0, 128;" :: "r"(id) : "memory")

__global__ void __launch_bounds__(BLK_T) fused_kernel(
    const float* __restrict__ x,      // (T,B,2)
    const float* __restrict__ raw,    // (B,34)
    float* __restrict__ out)          // (T,B,6)
{
    __shared__ __align__(16) float sred[SRED_FLOATS];
    const int tid = threadIdx.x;

    if (tid < 64) {
        // ====== producers: 1 chain/thread, short-chain (Y-state) form ======
        int bl = tid >> 3;
        int m  = tid & 7;
        int b  = blockIdx.x * 8 + bl;

        float a   = fmaf(raw[b*34 +      m], 0.9f, 0.1f);
        float bb  = fmaf(raw[b*34 +  8 + m], 450.0f, 50.0f);
        float c   = raw[b*34 + 16 + m];
        float d   = fmaf(raw[b*34 + 24 + m], 0.89f, 0.01f);

        float inv2a  = 0.5f / a;
        float binv2a = bb * inv2a;
        float boa    = bb / a;
        float nl2eob = -1.44269504088896f / bb;   // -log2(e)/b
        float onemc  = 1.0f - c;
        float inv1pd = 1.0f / (1.0f + d);

        // carried state: Y_prev and ef_prev, with S = Y_prev * ef_prev.
        // init S=50: Y_prev = 50, ef_prev = 1.
        float Yp  = 50.0f;
        float efp = 1.0f;
        float G   = 10.0f;

        float* my = sred + bl * BAS_S + m;

        const float2* __restrict__ xv = (const float2*)x;
        float2 cur[UG], nxt[UG];
#pragma unroll
        for (int i = 0; i < UG; ++i) cur[i] = __ldg(xv + i * B_LEN + b);

        for (int gi = 0; gi < NGROUPS; ++gi) {
            if (gi < NGROUPS - 1) {
                const float2* base = xv + (gi + 1) * UG * B_LEN + b;
#pragma unroll
                for (int i = 0; i < UG; ++i) nxt[i] = __ldg(base + i * B_LEN);
            }
            int slot = gi & 1;
            if (gi >= 2) BAR_SYNC(3 + slot);
            float* sb = my + slot * SLOT_S;
#pragma unroll
            for (int i = 0; i < UG; ++i) {
                float p   = cur[i].x;
                float pet = cur[i].y;

                // off-chain coefficients (depend on p and previous ef only)
                float c1 = fmaf(p, inv2a, binv2a);   // p/(2a) + b/(2a)
                float c2 = p * boa;                  // p*b/a
                float eA = efp * inv2a;
                float eB = efp * boa;

                // carried critical path: term -> arg -> fmax -> sqrt -> Y
                float term = fmaf(Yp, eA, c1);       // (p+S)/(2a)+b/(2a)
                float wboa = fmaf(Yp, eB, c2);       // (p+S)*b/a
                float arg  = fmaxf(fmaf(term, term, -wboa), NEARZERO);
                float Y    = term - f_sqrt_approx(arg);

                // off-chain epilogue
                float ef   = f_ex2(pet * nl2eob);    // exp(-pet/b), for next step
                float S    = Yp * efp;               // storage entering this step
                float W    = p + S;
                float avail = W - Y;
                float Snew = Y * ef;
                float vqs  = onemc * avail;
                float Gnew = fmaf(c, avail, G) * inv1pd;
                float vqg  = d * Gnew;
                float vae  = Y - Snew;
                G = Gnew;
                Yp = Y;
                efp = ef;

                float* sl = sb + i * STEP_S;
                sl[0 * Q_S] = vqs;
                sl[1 * Q_S] = vqg;
                sl[2 * Q_S] = vae;
                sl[3 * Q_S] = Snew;
                sl[4 * Q_S] = Gnew;
            }
            BAR_ARRIVE(1 + slot);
            if (gi < NGROUPS - 1) {
#pragma unroll
                for (int i = 0; i < UG; ++i) cur[i] = nxt[i];
            }
        }
    } else if (tid < 96) {
        // ========= warp2: inline convolution lanes =========
        int lane   = tid - 64;
        bool active = (lane < 16);
        int bl     = lane & 7;
        int series = lane >> 3;              // 0 = qsurf (q=0), 1 = qgw (q=1)
        int b      = blockIdx.x * 8 + bl;

        float uh[LENF];
        if (active) {
            float ra = raw[b * 34 + 32] * 2.9f;
            float rb = raw[b * 34 + 33] * 6.5f;
            float aa    = fmaxf(ra, 0.0f) + 0.1f;
            float theta = fmaxf(rb, 0.0f) + 0.5f;
            float lg   = lgammaf(aa);
            float lth  = logf(theta);
            float ivth = 1.0f / theta;
            float s = 0.0f;
#pragma unroll
            for (int k = 0; k < LENF; ++k) {
                float t = (float)k + 0.5f;
                float lw = (aa - 1.0f) * logf(t) - t * ivth - lg - aa * lth;
                uh[k] = expf(lw);
                s += uh[k];
            }
            float inv = 0.125f / s;          // fold the NMUL mean into the kernel
#pragma unroll
            for (int k = 0; k < LENF; ++k) uh[k] *= inv;
        } else {
#pragma unroll
            for (int k = 0; k < LENF; ++k) uh[k] = 0.0f;
        }

        float r[LENF - 1];
#pragma unroll
        for (int k = 0; k < LENF - 1; ++k) r[k] = 0.0f;

        const float* base0 = sred + bl * BAS_S + series * Q_S;

        for (int gi = 0; gi < NGROUPS; ++gi) {
            int slot = gi & 1;
            BAR_SYNC(1 + slot);
            if (active) {
                const float* sb = base0 + slot * SLOT_S;
                int tbase = gi * UG;
#pragma unroll
                for (int i = 0; i < UG; ++i) {
                    const float4* p4 = (const float4*)(sb + i * STEP_S);
                    float4 v0 = p4[0];
                    float4 v1 = p4[1];
                    float q = ((v0.x + v0.y) + (v0.z + v0.w))
                            + ((v1.x + v1.y) + (v1.z + v1.w));

                    float mine = fmaf(q, uh[0], r[0]);
#pragma unroll
                    for (int j = 0; j < LENF - 2; ++j)
                        r[j] = fmaf(q, uh[j + 1], r[j + 1]);
                    r[LENF - 2] = q * uh[LENF - 1];

                    float other = __shfl_xor_sync(0xffffu, mine, 8);
                    int t = tbase + i;
                    float* o = out + t * (6 * B_LEN) + b * 6;
                    if (series == 0) {
                        *(float2*)o = make_float2(mine + other, mine);
                    } else {
                        o[2] = mine;
                    }
                }
            }
            BAR_ARRIVE(3 + slot);
        }
    } else {
        // ========= warp3: plain mean lanes (cols 3,4,5) =========
        int lane = tid - 96;
        bool active = (lane < 24);
        int bl = lane & 7;
        int j  = lane >> 3;                  // 0: AET(q=2), 1: S(q=3), 2: G(q=4)
        int b  = blockIdx.x * 8 + bl;

        const float* base0 = sred + bl * BAS_S + (2 + j) * Q_S;

        for (int gi = 0; gi < NGROUPS; ++gi) {
            int slot = gi & 1;
            BAR_SYNC(1 + slot);
            if (active) {
                const float* sb = base0 + slot * SLOT_S;
                int tbase = gi * UG;
#pragma unroll
                for (int i = 0; i < UG; ++i) {
                    const float4* p4 = (const float4*)(sb + i * STEP_S);
                    float4 v0 = p4[0];
                    float4 v1 = p4[1];
                    float s = ((v0.x + v0.y) + (v0.z + v0.w))
                            + ((v1.x + v1.y) + (v1.z + v1.w));
                    int t = tbase + i;
                    out[t * (6 * B_LEN) + b * 6 + 3 + j] = s * 0.125f;
                }
            }
            BAR_ARRIVE(3 + slot);
        }
    }
}

// ---------------------------------------------------------------------------
extern "C" void kernel_launch(void* const* d_in, const int* in_sizes, int n_in,
                              void* d_out, int out_size) {
    const float* x   = (const float*)d_in[0];   // (730,1000,2)
    const float* raw = (const float*)d_in[1];   // (1000,34)
    float* out = (float*)d_out;                 // (730,1000,6)

    fused_kernel<<<NBLK, BLK_T>>>(x, raw, out);
}